// round 6
// baseline (speedup 1.0000x reference)
#include <cuda_runtime.h>

#define HW   512
#define TILE 32
#define RS   48   // raw tile (TILE + 2*8 halo)
#define MS   40   // intermediate (TILE + 2*4)
#define NTHREADS 256

__device__ __forceinline__ int refl(int i) {
    i = ::abs(i);
    return i < HW ? i : (2 * HW - 2 - i);
}

// asinh(x) = sign(x) * log(|x| + sqrt(x^2+1)); sqrt via v*rsqrt(v) (v>=1)
__device__ __forceinline__ float fast_asinh(float x) {
    float ax = fabsf(x);
    float v  = fmaf(ax, ax, 1.0f);
    float s  = v * rsqrtf(v);
    float r  = __logf(ax + s);
    return copysignf(r, x);
}

__global__ __launch_bounds__(NTHREADS, 7) void imgnorm_kernel(
    const float* __restrict__ img, const float* __restrict__ bg,
    const float* __restrict__ thr, const float* __restrict__ scl,
    float* __restrict__ out)
{
    __shared__ float sraw[RS][RS];      // raw with halo 8          9216 B
    __shared__ float shs_box[RS * MS];  // shs (ph2-3) / sbox2 (4.5+) 7680 B
    __shared__ float sres[MS][MS];      // raw - boxmean(raw)       6400 B
    __shared__ float shs2[MS][TILE];    // hsum9 of res^2           5120 B
#define SHS(r, c)  shs_box[(r) * MS + (c)]
#define SBOX(r, c) shs_box[(r) * TILE + (c)]

    const int bc  = blockIdx.z;            // b*5 + c
    const int tx0 = blockIdx.x * TILE;
    const int ty0 = blockIdx.y * TILE;
    const float* im  = img + (size_t)bc * HW * HW;
    const float* bgp = bg  + (size_t)bc * HW * HW;
    const int tid = threadIdx.x;
    const float inv81 = 1.0f / 81.0f;

    // Phase 1: load 48x48 raw tile. Interior blocks: vectorized LDG.128.
    const bool interior = (tx0 >= 8) && (tx0 + RS - 8 <= HW) &&
                          (ty0 >= 8) && (ty0 + RS - 8 <= HW);
    if (interior) {
        const float* base = im + (ty0 - 8) * HW + (tx0 - 8);
        for (int t = tid; t < RS * (RS / 4); t += NTHREADS) {   // 576 tasks
            int r = t / 12, c4 = (t - r * 12) * 4;
            *(float4*)&sraw[r][c4] = *(const float4*)&base[r * HW + c4];
        }
    } else {
        for (int i = tid; i < RS * RS; i += NTHREADS) {
            int r = i / RS, c = i - r * RS;
            sraw[r][c] = im[refl(ty0 + r - 8) * HW + refl(tx0 + c - 8)];
        }
    }
    __syncthreads();

    // Phase 2: horizontal 9-sums of raw, 48 rows x 40 cols (8 outs/task)
    for (int t = tid; t < RS * (MS / 8); t += NTHREADS) {   // 240 tasks
        int r = t / 5, c8 = (t - r * 5) * 8;
        float4 A = *(const float4*)&sraw[r][c8];
        float4 B = *(const float4*)&sraw[r][c8 + 4];
        float4 C = *(const float4*)&sraw[r][c8 + 8];
        float4 D = *(const float4*)&sraw[r][c8 + 12];
        float s0 = ((A.x + A.y) + (A.z + A.w)) + ((B.x + B.y) + (B.z + B.w)) + C.x;
        float s1 = s0 - A.x + C.y;
        float s2 = s1 - A.y + C.z;
        float s3 = s2 - A.z + C.w;
        float s4 = s3 - A.w + D.x;
        float s5 = s4 - B.x + D.y;
        float s6 = s5 - B.y + D.z;
        float s7 = s6 - B.z + D.w;
        *(float4*)&SHS(r, c8)     = make_float4(s0, s1, s2, s3);
        *(float4*)&SHS(r, c8 + 4) = make_float4(s4, s5, s6, s7);
    }
    __syncthreads();

    // Phase 3: vertical 9-sums -> mean -> res, 40x40.
    // Column ownership, 4-row sliding; only 6 window taps kept live.
    for (int t = tid; t < (MS / 4) * MS; t += NTHREADS) {   // 400 tasks
        int rg = t / MS, c = t - rg * MS;
        int r0 = rg * 4;
        float a0 = SHS(r0, c), a1 = SHS(r0 + 1, c), a2 = SHS(r0 + 2, c);
        float s = a0 + a1 + a2;
        #pragma unroll
        for (int k = 3; k < 9; k++) s += SHS(r0 + k, c);
        sres[r0 + 0][c] = sraw[r0 + 4][c + 4] - s * inv81;
        s += SHS(r0 + 9, c) - a0;
        sres[r0 + 1][c] = sraw[r0 + 5][c + 4] - s * inv81;
        s += SHS(r0 + 10, c) - a1;
        sres[r0 + 2][c] = sraw[r0 + 6][c + 4] - s * inv81;
        s += SHS(r0 + 11, c) - a2;
        sres[r0 + 3][c] = sraw[r0 + 7][c + 4] - s * inv81;
    }
    __syncthreads();

    // Phase 4: horizontal 9-sums of res^2, 40 rows x 32 cols (8 outs/task)
    for (int t = tid; t < MS * (TILE / 8); t += NTHREADS) { // 160 tasks
        int r = t >> 2, c8 = (t & 3) * 8;
        float4 A = *(const float4*)&sres[r][c8];
        float4 B = *(const float4*)&sres[r][c8 + 4];
        float4 C = *(const float4*)&sres[r][c8 + 8];
        float4 D = *(const float4*)&sres[r][c8 + 12];
        float q0 = A.x*A.x, q1 = A.y*A.y, q2  = A.z*A.z, q3  = A.w*A.w;
        float q4 = B.x*B.x, q5 = B.y*B.y, q6  = B.z*B.z, q7  = B.w*B.w;
        float q8 = C.x*C.x, q9 = C.y*C.y, q10 = C.z*C.z, q11 = C.w*C.w;
        float q12 = D.x*D.x, q13 = D.y*D.y, q14 = D.z*D.z, q15 = D.w*D.w;
        float s0 = ((q0 + q1) + (q2 + q3)) + ((q4 + q5) + (q6 + q7)) + q8;
        float s1 = s0 - q0 + q9;
        float s2 = s1 - q1 + q10;
        float s3 = s2 - q2 + q11;
        float s4 = s3 - q3 + q12;
        float s5 = s4 - q4 + q13;
        float s6 = s5 - q5 + q14;
        float s7 = s6 - q6 + q15;
        *(float4*)&shs2[r][c8]     = make_float4(s0, s1, s2, s3);
        *(float4*)&shs2[r][c8 + 4] = make_float4(s4, s5, s6, s7);
    }
    __syncthreads();

    // Phase 4.5: vertical 9-sum of shs2 -> SBOX (aliased over shs), 32x32.
    {
        int c  = tid & 31;
        int r0 = (tid >> 5) * 4;
        float a0 = shs2[r0][c], a1 = shs2[r0 + 1][c], a2 = shs2[r0 + 2][c];
        float s = a0 + a1 + a2;
        #pragma unroll
        for (int k = 3; k < 9; k++) s += shs2[r0 + k][c];
        float v0 = s;
        s += shs2[r0 + 9][c]  - a0;  float v1 = s;
        s += shs2[r0 + 10][c] - a1;  float v2 = s;
        s += shs2[r0 + 11][c] - a2;  float v3 = s;
        __syncthreads();             // shs reads (none remain) / writes ordered
        SBOX(r0 + 0, c) = v0;
        SBOX(r0 + 1, c) = v1;
        SBOX(r0 + 2, c) = v2;
        SBOX(r0 + 3, c) = v3;
    }
    __syncthreads();

    // Per-channel asinh constants (broadcast loads)
    const int cb = bc % 5;
    const float th0 = thr[cb * 3 + 0], th1 = thr[cb * 3 + 1], th2 = thr[cb * 3 + 2];
    const float sc0 = __expf(scl[cb * 3 + 0]);
    const float sc1 = __expf(scl[cb * 3 + 1]);
    const float sc2 = __expf(scl[cb * 3 + 2]);

    // Phase 5: row-wise, 4 adjacent pixels per thread — everything float4.
    const int row = tid >> 3;          // 0..31
    const int c4  = (tid & 7) << 2;    // 0..28
    const int gy  = ty0 + row;
    const int gx0 = tx0 + c4;
    const size_t CH = (size_t)HW * HW;
    const size_t p  = (size_t)bc * 7 * CH + (size_t)gy * HW + gx0;

    float raw[4], res[4], bgv[4], vv[4];
    *(float4*)raw = *(const float4*)&sraw[row + 8][c4 + 8];
    *(float4*)res = *(const float4*)&sres[row + 4][c4 + 4];
    *(float4*)vv  = *(const float4*)&SBOX(row, c4);
    *(float4*)bgv = *(const float4*)&bgp[(size_t)gy * HW + gx0];

    float l0[4], l1[4], cl[4], a0[4], a1[4], a2[4];
    #pragma unroll
    for (int j = 0; j < 4; j++) {
        float m = vv[j] * inv81;
        cl[j] = res[j] * rsqrtf(fmaxf(m, 1.0f));
        float off = (raw[j] - bgv[j]) * rsqrtf(bgv[j]);
        l0[j] = __logf(fmaxf(off + 1.0f, 1.0f));
        l1[j] = __logf(fmaxf(off,        1.0f));
        a0[j] = fast_asinh((raw[j] - th0) * sc0);
        a1[j] = fast_asinh((raw[j] - th1) * sc1);
        a2[j] = fast_asinh((raw[j] - th2) * sc2);
    }

    *(float4*)&out[p]          = *(float4*)raw;
    *(float4*)&out[p + 1 * CH] = *(float4*)l0;
    *(float4*)&out[p + 2 * CH] = *(float4*)l1;
    *(float4*)&out[p + 3 * CH] = *(float4*)cl;
    *(float4*)&out[p + 4 * CH] = *(float4*)a0;
    *(float4*)&out[p + 5 * CH] = *(float4*)a1;
    *(float4*)&out[p + 6 * CH] = *(float4*)a2;
}

extern "C" void kernel_launch(void* const* d_in, const int* in_sizes, int n_in,
                              void* d_out, int out_size) {
    const float* img = (const float*)d_in[0];
    const float* bg  = (const float*)d_in[1];
    const float* thr = (const float*)d_in[2];
    const float* scl = (const float*)d_in[3];
    float* out = (float*)d_out;
    dim3 grid(HW / TILE, HW / TILE, 8 * 5);
    imgnorm_kernel<<<grid, NTHREADS>>>(img, bg, thr, scl, out);
}

// round 7
// speedup vs baseline: 1.0786x; 1.0786x over previous
#include <cuda_runtime.h>

#define HW   512
#define TX   64
#define TY   32
#define RSX  80   // TX + 16
#define RSY  48   // TY + 16
#define MSX  72   // TX + 8
#define MSY  40   // TY + 8
#define NT   512

// dynamic smem layout (floats)
#define OFF_SRAW 0
#define OFF_SHS  (RSY * RSX)                 // 3840
#define OFF_SRES (OFF_SHS + RSY * MSX)       // 7296
#define OFF_SHS2 (OFF_SRES + MSY * MSX)      // 10176
#define SMEM_FLOATS (OFF_SHS2 + MSY * TX)    // 12736
#define SMEM_BYTES (SMEM_FLOATS * 4)         // 50944

__device__ __forceinline__ int refl(int i) {
    i = ::abs(i);
    return i < HW ? i : (2 * HW - 2 - i);
}

// asinh(x) = sign(x) * log(|x| + sqrt(x^2+1)); sqrt via v*rsqrt(v) (v>=1)
__device__ __forceinline__ float fast_asinh(float x) {
    float ax = fabsf(x);
    float v  = fmaf(ax, ax, 1.0f);
    float s  = v * rsqrtf(v);
    float r  = __logf(ax + s);
    return copysignf(r, x);
}

__global__ __launch_bounds__(NT) void imgnorm_kernel(
    const float* __restrict__ img, const float* __restrict__ bg,
    const float* __restrict__ thr, const float* __restrict__ scl,
    float* __restrict__ out)
{
    extern __shared__ float smem[];
    float* sraw = smem + OFF_SRAW;   // [48][80]
    float* shs  = smem + OFF_SHS;    // [48][72]  (aliased as sbox [32][64] after phase 3)
    float* sres = smem + OFF_SRES;   // [40][72]
    float* shs2 = smem + OFF_SHS2;   // [40][64]
#define SRAW(r, c) sraw[(r) * RSX + (c)]
#define SHS(r, c)  shs [(r) * MSX + (c)]
#define SBOX(r, c) shs [(r) * TX  + (c)]
#define SRES(r, c) sres[(r) * MSX + (c)]
#define SHS2(r, c) shs2[(r) * TX  + (c)]

    const int bc  = blockIdx.z;            // b*5 + c
    const int tx0 = blockIdx.x * TX;
    const int ty0 = blockIdx.y * TY;
    const float* im  = img + (size_t)bc * HW * HW;
    const float* bgp = bg  + (size_t)bc * HW * HW;
    const int tid = threadIdx.x;
    const float inv81 = 1.0f / 81.0f;

    // Phase 1: load 48x80 raw tile. Interior blocks: vectorized LDG.128.
    const bool interior = (tx0 >= 8) && (tx0 + RSX - 8 <= HW) &&
                          (ty0 >= 8) && (ty0 + RSY - 8 <= HW);
    if (interior) {
        const float* base = im + (ty0 - 8) * HW + (tx0 - 8);
        for (int t = tid; t < RSY * (RSX / 4); t += NT) {       // 960 tasks
            int r = t / 20, c4 = (t - r * 20) * 4;
            *(float4*)&SRAW(r, c4) = *(const float4*)&base[r * HW + c4];
        }
    } else {
        for (int i = tid; i < RSY * RSX; i += NT) {             // 3840 tasks
            int r = i / RSX, c = i - r * RSX;
            SRAW(r, c) = im[refl(ty0 + r - 8) * HW + refl(tx0 + c - 8)];
        }
    }
    __syncthreads();

    // Phase 2: horizontal 9-sums of raw, 48 rows x 72 cols (4 outs/task, contiguous)
    for (int t = tid; t < RSY * (MSX / 4); t += NT) {           // 864 tasks
        int r = t / 18, c4 = (t - r * 18) * 4;
        float4 a = *(const float4*)&SRAW(r, c4);
        float4 b = *(const float4*)&SRAW(r, c4 + 4);
        float4 c = *(const float4*)&SRAW(r, c4 + 8);
        float s0 = ((a.x + a.y) + (a.z + a.w)) + ((b.x + b.y) + (b.z + b.w)) + c.x;
        float s1 = s0 - a.x + c.y;
        float s2 = s1 - a.y + c.z;
        float s3 = s2 - a.z + c.w;
        *(float4*)&SHS(r, c4) = make_float4(s0, s1, s2, s3);
    }
    __syncthreads();

    // Phase 3: vertical 9-sums -> mean -> res, 40x72.
    // Column ownership, 4-row register sliding window.
    for (int t = tid; t < (MSY / 4) * MSX; t += NT) {           // 720 tasks
        int rg = t / MSX, c = t - rg * MSX;
        int r0 = rg * 4;
        float a0 = SHS(r0, c), a1 = SHS(r0 + 1, c), a2 = SHS(r0 + 2, c);
        float s = a0 + a1 + a2;
        #pragma unroll
        for (int k = 3; k < 9; k++) s += SHS(r0 + k, c);
        SRES(r0 + 0, c) = SRAW(r0 + 4, c + 4) - s * inv81;
        s += SHS(r0 + 9, c) - a0;
        SRES(r0 + 1, c) = SRAW(r0 + 5, c + 4) - s * inv81;
        s += SHS(r0 + 10, c) - a1;
        SRES(r0 + 2, c) = SRAW(r0 + 6, c + 4) - s * inv81;
        s += SHS(r0 + 11, c) - a2;
        SRES(r0 + 3, c) = SRAW(r0 + 7, c + 4) - s * inv81;
    }
    __syncthreads();

    // Phase 4: horizontal 9-sums of res^2, 40 rows x 64 cols (4 outs/task, contiguous)
    for (int t = tid; t < MSY * (TX / 4); t += NT) {            // 640 tasks
        int r = t >> 4, c4 = (t & 15) * 4;
        float4 a = *(const float4*)&SRES(r, c4);
        float4 b = *(const float4*)&SRES(r, c4 + 4);
        float4 c = *(const float4*)&SRES(r, c4 + 8);
        float q0 = a.x*a.x, q1 = a.y*a.y, q2 = a.z*a.z, q3 = a.w*a.w;
        float q4 = b.x*b.x, q5 = b.y*b.y, q6 = b.z*b.z, q7 = b.w*b.w;
        float q8 = c.x*c.x, q9 = c.y*c.y, q10 = c.z*c.z, q11 = c.w*c.w;
        float s0 = ((q0 + q1) + (q2 + q3)) + ((q4 + q5) + (q6 + q7)) + q8;
        float s1 = s0 - q0 + q9;
        float s2 = s1 - q1 + q10;
        float s3 = s2 - q2 + q11;
        *(float4*)&SHS2(r, c4) = make_float4(s0, s1, s2, s3);
    }
    __syncthreads();

    // Phase 4.5: vertical 9-sum of shs2 -> SBOX (aliased over shs), 32x64.
    // Exactly 1 task/thread. (shs last read in phase 3; two syncs since — safe.)
    {
        int c  = tid & 63;
        int r0 = (tid >> 6) * 4;
        float a0 = SHS2(r0, c), a1 = SHS2(r0 + 1, c), a2 = SHS2(r0 + 2, c);
        float s = a0 + a1 + a2;
        #pragma unroll
        for (int k = 3; k < 9; k++) s += SHS2(r0 + k, c);
        SBOX(r0 + 0, c) = s;
        s += SHS2(r0 + 9, c)  - a0;
        SBOX(r0 + 1, c) = s;
        s += SHS2(r0 + 10, c) - a1;
        SBOX(r0 + 2, c) = s;
        s += SHS2(r0 + 11, c) - a2;
        SBOX(r0 + 3, c) = s;
    }
    __syncthreads();

    // Per-channel asinh constants (broadcast loads)
    const int cb = bc % 5;
    const float th0 = thr[cb * 3 + 0], th1 = thr[cb * 3 + 1], th2 = thr[cb * 3 + 2];
    const float sc0 = __expf(scl[cb * 3 + 0]);
    const float sc1 = __expf(scl[cb * 3 + 1]);
    const float sc2 = __expf(scl[cb * 3 + 2]);

    // Phase 5: row-wise, 4 adjacent pixels per thread — everything float4.
    const int row = tid >> 4;          // 0..31
    const int c4  = (tid & 15) << 2;   // 0..60
    const int gy  = ty0 + row;
    const int gx0 = tx0 + c4;
    const size_t CH = (size_t)HW * HW;
    const size_t p  = (size_t)bc * 7 * CH + (size_t)gy * HW + gx0;

    float raw[4], res[4], bgv[4], vv[4];
    *(float4*)raw = *(const float4*)&SRAW(row + 8, c4 + 8);
    *(float4*)res = *(const float4*)&SRES(row + 4, c4 + 4);
    *(float4*)vv  = *(const float4*)&SBOX(row, c4);
    *(float4*)bgv = *(const float4*)&bgp[(size_t)gy * HW + gx0];

    float l0[4], l1[4], cl[4], a0[4], a1[4], a2[4];
    #pragma unroll
    for (int j = 0; j < 4; j++) {
        float m = vv[j] * inv81;
        cl[j] = res[j] * rsqrtf(fmaxf(m, 1.0f));
        float off = (raw[j] - bgv[j]) * rsqrtf(bgv[j]);
        l0[j] = __logf(fmaxf(off + 1.0f, 1.0f));
        l1[j] = __logf(fmaxf(off,        1.0f));
        a0[j] = fast_asinh((raw[j] - th0) * sc0);
        a1[j] = fast_asinh((raw[j] - th1) * sc1);
        a2[j] = fast_asinh((raw[j] - th2) * sc2);
    }

    *(float4*)&out[p]          = *(float4*)raw;
    *(float4*)&out[p + 1 * CH] = *(float4*)l0;
    *(float4*)&out[p + 2 * CH] = *(float4*)l1;
    *(float4*)&out[p + 3 * CH] = *(float4*)cl;
    *(float4*)&out[p + 4 * CH] = *(float4*)a0;
    *(float4*)&out[p + 5 * CH] = *(float4*)a1;
    *(float4*)&out[p + 6 * CH] = *(float4*)a2;
}

extern "C" void kernel_launch(void* const* d_in, const int* in_sizes, int n_in,
                              void* d_out, int out_size) {
    const float* img = (const float*)d_in[0];
    const float* bg  = (const float*)d_in[1];
    const float* thr = (const float*)d_in[2];
    const float* scl = (const float*)d_in[3];
    float* out = (float*)d_out;
    cudaFuncSetAttribute(imgnorm_kernel,
                         cudaFuncAttributeMaxDynamicSharedMemorySize, SMEM_BYTES);
    dim3 grid(HW / TX, HW / TY, 8 * 5);
    imgnorm_kernel<<<grid, NT, SMEM_BYTES>>>(img, bg, thr, scl, out);
}